// round 3
// baseline (speedup 1.0000x reference)
#include <cuda_runtime.h>

#define DIM 1024
#define HEADS 16
#define DH 64
#define SEQ 2048
#define NB 2
#define ROWS (NB * SEQ)        // 4096
#define SCALE 0.125f           // 64^-0.5
#define LNEPS 1e-5f

// ---------------- scratch (static device globals; no allocation) ----------------
__device__ float g_xn[ROWS * DIM];     // layernorm output [4096,1024]
__device__ float g_q[ROWS * DIM];      // [b*H + h][n][dh]
__device__ float g_k[ROWS * DIM];
__device__ float g_v[ROWS * DIM];
__device__ float g_attn[ROWS * DIM];   // attention out, heads re-merged [4096,1024]
__device__ float g_wcomb[DIM * DIM];   // wo @ w_out

// ---------------- LayerNorm ----------------
__global__ void __launch_bounds__(256) ln_kernel(const float* __restrict__ x,
                                                 const float* __restrict__ gamma,
                                                 const float* __restrict__ beta)
{
    int row = blockIdx.x;
    int t = threadIdx.x;
    const float4* xr = (const float4*)(x + (size_t)row * DIM);
    float4 v = xr[t];
    float s = v.x + v.y + v.z + v.w;
    float ss = v.x * v.x + v.y * v.y + v.z * v.z + v.w * v.w;
    #pragma unroll
    for (int o = 16; o > 0; o >>= 1) {
        s  += __shfl_xor_sync(0xffffffffu, s, o);
        ss += __shfl_xor_sync(0xffffffffu, ss, o);
    }
    __shared__ float sb[8], ssb[8];
    int w = t >> 5, ln = t & 31;
    if (ln == 0) { sb[w] = s; ssb[w] = ss; }
    __syncthreads();
    float tot = 0.f, tot2 = 0.f;
    #pragma unroll
    for (int i = 0; i < 8; i++) { tot += sb[i]; tot2 += ssb[i]; }
    float mu = tot * (1.f / DIM);
    float var = tot2 * (1.f / DIM) - mu * mu;
    float rs = rsqrtf(var + LNEPS);
    float4 g = ((const float4*)gamma)[t];
    float4 bb = ((const float4*)beta)[t];
    float4 o;
    o.x = (v.x - mu) * rs * g.x + bb.x;
    o.y = (v.y - mu) * rs * g.y + bb.y;
    o.z = (v.z - mu) * rs * g.z + bb.z;
    o.w = (v.w - mu) * rs * g.w + bb.w;
    ((float4*)(g_xn + (size_t)row * DIM))[t] = o;
}

// ---------------- shared GEMM core: 64x64 block tile, 4x4 per thread ----------------
// C_tile = A[row0:row0+64, :K] @ Bw[:K, col0:col0+64]
__device__ __forceinline__ void gemm_core(const float* __restrict__ A,
                                          const float* __restrict__ Bw,
                                          int K, int N, float acc[4][4])
{
    __shared__ float As[64][20];   // [m][k], padded
    __shared__ float Bs[16][68];   // [k][n], padded
    const int t = threadIdx.x;
    const int ty = t >> 4, tx = t & 15;
    const int row0 = blockIdx.y * 64;
    const int col0 = blockIdx.x * 64;
    const int arow = t >> 2, ac = (t & 3) * 4;     // A tile 64x16 loader
    const int brow = t >> 4, bc = (t & 15) * 4;    // B tile 16x64 loader
    const float* Ap = A + (size_t)(row0 + arow) * K + ac;
    const float* Bp = Bw + (size_t)brow * N + col0 + bc;

    for (int k0 = 0; k0 < K; k0 += 16) {
        float4 av = *(const float4*)(Ap + k0);
        float4 bv = *(const float4*)(Bp + (size_t)k0 * N);
        __syncthreads();
        *(float4*)&As[arow][ac] = av;
        *(float4*)&Bs[brow][bc] = bv;
        __syncthreads();
        #pragma unroll
        for (int kk = 0; kk < 16; kk++) {
            float a[4], b[4];
            #pragma unroll
            for (int i = 0; i < 4; i++) a[i] = As[ty * 4 + i][kk];
            float4 bvv = *(const float4*)&Bs[kk][tx * 4];
            b[0] = bvv.x; b[1] = bvv.y; b[2] = bvv.z; b[3] = bvv.w;
            #pragma unroll
            for (int i = 0; i < 4; i++)
                #pragma unroll
                for (int j = 0; j < 4; j++)
                    acc[i][j] += a[i] * b[j];
        }
    }
}

// ---------------- QKV projection: xn @ {wq,wk,wv} -> head-split layout ----------------
__global__ void __launch_bounds__(256) gemm_qkv_kernel(const float* __restrict__ wq,
                                                       const float* __restrict__ wk,
                                                       const float* __restrict__ wv)
{
    const float* W = (blockIdx.z == 0) ? wq : (blockIdx.z == 1) ? wk : wv;
    float acc[4][4] = {};
    gemm_core(g_xn, W, DIM, DIM, acc);
    float* dst = (blockIdx.z == 0) ? g_q : (blockIdx.z == 1) ? g_k : g_v;
    int ty = threadIdx.x >> 4, tx = threadIdx.x & 15;
    int c = blockIdx.x * 64 + tx * 4;
    int h = c >> 6, dh = c & 63;
    #pragma unroll
    for (int i = 0; i < 4; i++) {
        int m = blockIdx.y * 64 + ty * 4 + i;
        int b = m >> 11, n = m & (SEQ - 1);
        float4 o = make_float4(acc[i][0], acc[i][1], acc[i][2], acc[i][3]);
        *(float4*)(dst + ((size_t)(b * HEADS + h) * SEQ + n) * DH + dh) = o;
    }
}

// ---------------- wcomb = wo @ w_out ----------------
__global__ void __launch_bounds__(256) gemm_wcomb_kernel(const float* __restrict__ wo,
                                                         const float* __restrict__ wout)
{
    float acc[4][4] = {};
    gemm_core(wo, wout, DIM, DIM, acc);
    int ty = threadIdx.x >> 4, tx = threadIdx.x & 15;
    int c = blockIdx.x * 64 + tx * 4;
    #pragma unroll
    for (int i = 0; i < 4; i++) {
        int r = blockIdx.y * 64 + ty * 4 + i;
        float4 o = make_float4(acc[i][0], acc[i][1], acc[i][2], acc[i][3]);
        *(float4*)(g_wcomb + (size_t)r * DIM + c) = o;
    }
}

// ---------------- final projection: attn @ wcomb + b_out ----------------
__global__ void __launch_bounds__(256) gemm_out_kernel(const float* __restrict__ bias,
                                                       float* __restrict__ C)
{
    float acc[4][4] = {};
    gemm_core(g_attn, g_wcomb, DIM, DIM, acc);
    int ty = threadIdx.x >> 4, tx = threadIdx.x & 15;
    int c = blockIdx.x * 64 + tx * 4;
    float4 bb = *(const float4*)(bias + c);
    #pragma unroll
    for (int i = 0; i < 4; i++) {
        int r = blockIdx.y * 64 + ty * 4 + i;
        float4 o = make_float4(acc[i][0] + bb.x, acc[i][1] + bb.y,
                               acc[i][2] + bb.z, acc[i][3] + bb.w);
        *(float4*)(C + (size_t)r * DIM + c) = o;
    }
}

// ---------------- fused flash attention ----------------
// grid: (SEQ/64 q-tiles, NB*HEADS), block 256 threads.
// Thread (ty=t/16, tx=t%16) owns S/O tile rows ty*4..+3, cols tx*4..+3.
// Row group = half-warp -> shuffle reductions. P stays in registers,
// redistributed to the P@V product via __shfl_sync.
__global__ void __launch_bounds__(256) attn_kernel()
{
    __shared__ float Qs[64][65];   // [r][d], pre-scaled by SCALE
    __shared__ float KVs[64][65];  // [c][d], K then V per tile

    const int t = threadIdx.x;
    const int ty = t >> 4, tx = t & 15;
    const int lane = t & 31;
    const int half = lane & 16;
    const int q0 = blockIdx.x * 64;
    const int bh = blockIdx.y;

    const float* qbase = g_q + (size_t)bh * SEQ * DH;
    const float* kbase = g_k + (size_t)bh * SEQ * DH;
    const float* vbase = g_v + (size_t)bh * SEQ * DH;

    // load Q tile (scaled)
    #pragma unroll
    for (int it = 0; it < 4; it++) {
        int r = (t >> 4) + it * 16;
        int d = (t & 15) * 4;
        float4 qv = *(const float4*)(qbase + (size_t)(q0 + r) * DH + d);
        Qs[r][d + 0] = qv.x * SCALE;
        Qs[r][d + 1] = qv.y * SCALE;
        Qs[r][d + 2] = qv.z * SCALE;
        Qs[r][d + 3] = qv.w * SCALE;
    }

    float m[4], l[4], o[4][4];
    #pragma unroll
    for (int i = 0; i < 4; i++) {
        m[i] = -1e30f; l[i] = 0.f;
        #pragma unroll
        for (int j = 0; j < 4; j++) o[i][j] = 0.f;
    }

    for (int kt = 0; kt < SEQ / 64; kt++) {
        __syncthreads();   // protect KVs (V) from previous iteration
        // load K tile
        #pragma unroll
        for (int it = 0; it < 4; it++) {
            int c = (t >> 4) + it * 16;
            int d = (t & 15) * 4;
            float4 kv = *(const float4*)(kbase + (size_t)(kt * 64 + c) * DH + d);
            KVs[c][d + 0] = kv.x; KVs[c][d + 1] = kv.y;
            KVs[c][d + 2] = kv.z; KVs[c][d + 3] = kv.w;
        }
        __syncthreads();

        // S = Q K^T (Q pre-scaled)
        float s[4][4] = {};
        #pragma unroll 8
        for (int d = 0; d < 64; d++) {
            float a[4], b[4];
            #pragma unroll
            for (int i = 0; i < 4; i++) a[i] = Qs[ty * 4 + i][d];
            #pragma unroll
            for (int j = 0; j < 4; j++) b[j] = KVs[tx * 4 + j][d];
            #pragma unroll
            for (int i = 0; i < 4; i++)
                #pragma unroll
                for (int j = 0; j < 4; j++)
                    s[i][j] += a[i] * b[j];
        }

        // online softmax update (row reductions over half-warp)
        #pragma unroll
        for (int i = 0; i < 4; i++) {
            float rmax = fmaxf(fmaxf(s[i][0], s[i][1]), fmaxf(s[i][2], s[i][3]));
            #pragma unroll
            for (int msk = 1; msk <= 8; msk <<= 1)
                rmax = fmaxf(rmax, __shfl_xor_sync(0xffffffffu, rmax, msk));
            float mn = fmaxf(m[i], rmax);
            float corr = __expf(m[i] - mn);
            m[i] = mn;
            float rs = 0.f;
            #pragma unroll
            for (int j = 0; j < 4; j++) {
                s[i][j] = __expf(s[i][j] - mn);
                rs += s[i][j];
            }
            #pragma unroll
            for (int msk = 1; msk <= 8; msk <<= 1)
                rs += __shfl_xor_sync(0xffffffffu, rs, msk);
            l[i] = l[i] * corr + rs;
            #pragma unroll
            for (int j = 0; j < 4; j++) o[i][j] *= corr;
        }

        __syncthreads();   // done reading K from KVs
        // load V tile into same buffer
        #pragma unroll
        for (int it = 0; it < 4; it++) {
            int c = (t >> 4) + it * 16;
            int d = (t & 15) * 4;
            float4 vv = *(const float4*)(vbase + (size_t)(kt * 64 + c) * DH + d);
            KVs[c][d + 0] = vv.x; KVs[c][d + 1] = vv.y;
            KVs[c][d + 2] = vv.z; KVs[c][d + 3] = vv.w;
        }
        __syncthreads();

        // O += P @ V ; P redistributed via shuffles from register tiles
        #pragma unroll 4
        for (int c4 = 0; c4 < 16; c4++) {
            int src = half | c4;
            #pragma unroll
            for (int jj = 0; jj < 4; jj++) {
                int cc = c4 * 4 + jj;
                float p[4], v[4];
                #pragma unroll
                for (int i = 0; i < 4; i++)
                    p[i] = __shfl_sync(0xffffffffu, s[i][jj], src);
                #pragma unroll
                for (int j = 0; j < 4; j++)
                    v[j] = KVs[cc][tx * 4 + j];
                #pragma unroll
                for (int i = 0; i < 4; i++)
                    #pragma unroll
                    for (int j = 0; j < 4; j++)
                        o[i][j] += p[i] * v[j];
            }
        }
    }

    // normalize and write out, re-merging heads: [b][n][h*64+dh]
    int bq = bh >> 4;
    int h = bh & 15;
    #pragma unroll
    for (int i = 0; i < 4; i++) {
        float inv = 1.0f / l[i];
        int n = q0 + ty * 4 + i;
        float4 ov = make_float4(o[i][0] * inv, o[i][1] * inv,
                                o[i][2] * inv, o[i][3] * inv);
        *(float4*)(g_attn + ((size_t)bq * SEQ + n) * DIM + h * 64 + tx * 4) = ov;
    }
}

// ---------------- launch ----------------
extern "C" void kernel_launch(void* const* d_in, const int* in_sizes, int n_in,
                              void* d_out, int out_size)
{
    const float* x     = (const float*)d_in[0];
    const float* gamma = (const float*)d_in[1];
    const float* beta  = (const float*)d_in[2];
    const float* wq    = (const float*)d_in[3];
    const float* wk    = (const float*)d_in[4];
    const float* wv    = (const float*)d_in[5];
    const float* wo    = (const float*)d_in[6];
    const float* w_out = (const float*)d_in[7];
    const float* b_out = (const float*)d_in[8];
    float* out = (float*)d_out;

    ln_kernel<<<ROWS, 256>>>(x, gamma, beta);
    gemm_wcomb_kernel<<<dim3(DIM / 64, DIM / 64), 256>>>(wo, w_out);
    gemm_qkv_kernel<<<dim3(DIM / 64, ROWS / 64, 3), 256>>>(wq, wk, wv);
    attn_kernel<<<dim3(SEQ / 64, NB * HEADS), 256>>>();
    gemm_out_kernel<<<dim3(DIM / 64, ROWS / 64), 256>>>(b_out, out);
}

// round 4
// speedup vs baseline: 3.4164x; 3.4164x over previous
#include <cuda_runtime.h>
#include <cstdint>

#define DIM 1024
#define HEADS 16
#define DH 64
#define SEQ 2048
#define NB 2
#define ROWS (NB * SEQ)        // 4096
#define SCALE 0.125f
#define LNEPS 1e-5f

// ---------------- scratch ----------------
__device__ float g_xn[ROWS * DIM];
__device__ float g_q[ROWS * DIM];      // tf32 bits, pre-scaled; [b*H+h][n][dh]
__device__ float g_k[ROWS * DIM];      // tf32 bits
__device__ float g_v[ROWS * DIM];      // tf32 bits
__device__ float g_attn[ROWS * DIM];   // fp32, heads re-merged [4096,1024]
__device__ float g_wcomb[DIM * DIM];   // wo @ w_out (fp32)

// ---------------- tf32 helpers ----------------
__device__ __forceinline__ unsigned f2tf(float x) {
    unsigned u;
    asm("cvt.rna.tf32.f32 %0, %1;" : "=r"(u) : "f"(x));
    return u;
}
__device__ __forceinline__ void mma8(float* c, const unsigned* a, unsigned b0, unsigned b1) {
    asm volatile(
        "mma.sync.aligned.m16n8k8.row.col.f32.tf32.tf32.f32 "
        "{%0,%1,%2,%3}, {%4,%5,%6,%7}, {%8,%9}, {%0,%1,%2,%3};\n"
        : "+f"(c[0]), "+f"(c[1]), "+f"(c[2]), "+f"(c[3])
        : "r"(a[0]), "r"(a[1]), "r"(a[2]), "r"(a[3]), "r"(b0), "r"(b1));
}

// ---------------- LayerNorm ----------------
__global__ void __launch_bounds__(256) ln_kernel(const float* __restrict__ x,
                                                 const float* __restrict__ gamma,
                                                 const float* __restrict__ beta)
{
    int row = blockIdx.x;
    int t = threadIdx.x;
    const float4* xr = (const float4*)(x + (size_t)row * DIM);
    float4 v = xr[t];
    float s = v.x + v.y + v.z + v.w;
    float ss = v.x * v.x + v.y * v.y + v.z * v.z + v.w * v.w;
    #pragma unroll
    for (int o = 16; o > 0; o >>= 1) {
        s  += __shfl_xor_sync(0xffffffffu, s, o);
        ss += __shfl_xor_sync(0xffffffffu, ss, o);
    }
    __shared__ float sb[8], ssb[8];
    int w = t >> 5, ln = t & 31;
    if (ln == 0) { sb[w] = s; ssb[w] = ss; }
    __syncthreads();
    float tot = 0.f, tot2 = 0.f;
    #pragma unroll
    for (int i = 0; i < 8; i++) { tot += sb[i]; tot2 += ssb[i]; }
    float mu = tot * (1.f / DIM);
    float var = tot2 * (1.f / DIM) - mu * mu;
    float rs = rsqrtf(var + LNEPS);
    float4 g = ((const float4*)gamma)[t];
    float4 bb = ((const float4*)beta)[t];
    float4 o;
    o.x = (v.x - mu) * rs * g.x + bb.x;
    o.y = (v.y - mu) * rs * g.y + bb.y;
    o.z = (v.z - mu) * rs * g.z + bb.z;
    o.w = (v.w - mu) * rs * g.w + bb.w;
    ((float4*)(g_xn + (size_t)row * DIM))[t] = o;
}

// ---------------- tf32 tensor-core GEMM core ----------------
// C tile (BMxBN) = A[row0:+BM, :K] @ B[:K, col0:+BN], 256 threads, 8 warps.
// Warp layout 4x2 (wm rows, wn cols); warp computes 32x64 via m16n8k8 tiles.
#define BM 128
#define BN 128
#define BK 32
#define APAD 36     // (row*36 + col) % 32 = 4*row + col  -> conflict-free frags
#define BPAD 136    // (row*136 + col) % 32 = 8*row + col -> conflict-free frags

__device__ __forceinline__ void gemm_tc_core(const float* __restrict__ A,
                                             const float* __restrict__ B,
                                             int K, int N, float acc[2][8][4])
{
    __shared__ unsigned As[BM][APAD];
    __shared__ unsigned Bs[BK][BPAD];
    const int t = threadIdx.x;
    const int wid = t >> 5, lane = t & 31;
    const int g = lane >> 2, q4 = lane & 3;
    const int wm = wid & 3, wn = wid >> 2;
    const int row0 = blockIdx.y * BM, col0 = blockIdx.x * BN;

    const int arow = t >> 3, acol = (t & 7) * 4;    // A panel 128x32
    const int brow = t >> 5, bcol = (t & 31) * 4;   // B panel 32x128

    const float* Ap = A + (size_t)(row0 + arow) * K + acol;
    const float* Bp = B + (size_t)brow * N + col0 + bcol;

    float4 la[4], lb[4];
    #pragma unroll
    for (int i = 0; i < 4; i++) la[i] = *(const float4*)(Ap + (size_t)(32 * i) * K);
    #pragma unroll
    for (int i = 0; i < 4; i++) lb[i] = *(const float4*)(Bp + (size_t)(8 * i) * N);

    for (int k0 = 0; k0 < K; k0 += BK) {
        __syncthreads();
        #pragma unroll
        for (int i = 0; i < 4; i++) {
            uint4 vv;
            vv.x = f2tf(la[i].x); vv.y = f2tf(la[i].y);
            vv.z = f2tf(la[i].z); vv.w = f2tf(la[i].w);
            *(uint4*)&As[arow + 32 * i][acol] = vv;
        }
        #pragma unroll
        for (int i = 0; i < 4; i++) {
            uint4 vv;
            vv.x = f2tf(lb[i].x); vv.y = f2tf(lb[i].y);
            vv.z = f2tf(lb[i].z); vv.w = f2tf(lb[i].w);
            *(uint4*)&Bs[brow + 8 * i][bcol] = vv;
        }
        __syncthreads();
        if (k0 + BK < K) {
            #pragma unroll
            for (int i = 0; i < 4; i++)
                la[i] = *(const float4*)(Ap + k0 + BK + (size_t)(32 * i) * K);
            #pragma unroll
            for (int i = 0; i < 4; i++)
                lb[i] = *(const float4*)(Bp + (size_t)(k0 + BK + 8 * i) * N);
        }
        #pragma unroll
        for (int kk = 0; kk < 4; kk++) {
            unsigned af[2][4];
            #pragma unroll
            for (int mt = 0; mt < 2; mt++) {
                int r = wm * 32 + mt * 16;
                af[mt][0] = As[r + g][kk * 8 + q4];
                af[mt][1] = As[r + g + 8][kk * 8 + q4];
                af[mt][2] = As[r + g][kk * 8 + q4 + 4];
                af[mt][3] = As[r + g + 8][kk * 8 + q4 + 4];
            }
            #pragma unroll
            for (int nt = 0; nt < 8; nt++) {
                int cb = wn * 64 + nt * 8 + g;
                unsigned b0 = Bs[kk * 8 + q4][cb];
                unsigned b1 = Bs[kk * 8 + q4 + 4][cb];
                mma8(acc[0][nt], af[0], b0, b1);
                mma8(acc[1][nt], af[1], b0, b1);
            }
        }
    }
}

// ---------------- QKV projection (tf32 epilogue, head-split, Q pre-scaled) ----------------
__global__ void __launch_bounds__(256) gemm_qkv(const float* __restrict__ wq,
                                                const float* __restrict__ wk,
                                                const float* __restrict__ wv)
{
    float acc[2][8][4] = {};
    const float* W = (blockIdx.z == 0) ? wq : (blockIdx.z == 1) ? wk : wv;
    gemm_tc_core(g_xn, W, DIM, DIM, acc);
    float* dst = (blockIdx.z == 0) ? g_q : (blockIdx.z == 1) ? g_k : g_v;
    float sc = (blockIdx.z == 0) ? SCALE : 1.f;

    const int t = threadIdx.x, wid = t >> 5, lane = t & 31;
    const int g = lane >> 2, q4 = lane & 3;
    const int wm = wid & 3, wn = wid >> 2;
    #pragma unroll
    for (int mt = 0; mt < 2; mt++) {
        #pragma unroll
        for (int nt = 0; nt < 8; nt++) {
            int cglob = blockIdx.x * BN + wn * 64 + nt * 8 + q4 * 2;
            int h = cglob >> 6, dh = cglob & 63;
            #pragma unroll
            for (int half = 0; half < 2; half++) {
                int m = blockIdx.y * BM + wm * 32 + mt * 16 + g + half * 8;
                int b = m >> 11, n = m & (SEQ - 1);
                float2 o;
                o.x = __uint_as_float(f2tf(acc[mt][nt][half * 2 + 0] * sc));
                o.y = __uint_as_float(f2tf(acc[mt][nt][half * 2 + 1] * sc));
                *(float2*)(dst + ((size_t)(b * HEADS + h) * SEQ + n) * DH + dh) = o;
            }
        }
    }
}

// ---------------- wcomb = wo @ w_out ----------------
__global__ void __launch_bounds__(256) gemm_wcomb(const float* __restrict__ wo,
                                                  const float* __restrict__ wout)
{
    float acc[2][8][4] = {};
    gemm_tc_core(wo, wout, DIM, DIM, acc);
    const int t = threadIdx.x, wid = t >> 5, lane = t & 31;
    const int g = lane >> 2, q4 = lane & 3;
    const int wm = wid & 3, wn = wid >> 2;
    #pragma unroll
    for (int mt = 0; mt < 2; mt++) {
        #pragma unroll
        for (int nt = 0; nt < 8; nt++) {
            int c = blockIdx.x * BN + wn * 64 + nt * 8 + q4 * 2;
            #pragma unroll
            for (int half = 0; half < 2; half++) {
                int r = blockIdx.y * BM + wm * 32 + mt * 16 + g + half * 8;
                float2 o = make_float2(acc[mt][nt][half * 2 + 0], acc[mt][nt][half * 2 + 1]);
                *(float2*)(g_wcomb + (size_t)r * DIM + c) = o;
            }
        }
    }
}

// ---------------- final projection: attn @ wcomb + b_out ----------------
__global__ void __launch_bounds__(256) gemm_out(const float* __restrict__ bias,
                                                float* __restrict__ C)
{
    float acc[2][8][4] = {};
    gemm_tc_core(g_attn, g_wcomb, DIM, DIM, acc);
    const int t = threadIdx.x, wid = t >> 5, lane = t & 31;
    const int g = lane >> 2, q4 = lane & 3;
    const int wm = wid & 3, wn = wid >> 2;
    #pragma unroll
    for (int mt = 0; mt < 2; mt++) {
        #pragma unroll
        for (int nt = 0; nt < 8; nt++) {
            int c = blockIdx.x * BN + wn * 64 + nt * 8 + q4 * 2;
            float2 bb = *(const float2*)(bias + c);
            #pragma unroll
            for (int half = 0; half < 2; half++) {
                int r = blockIdx.y * BM + wm * 32 + mt * 16 + g + half * 8;
                float2 o = make_float2(acc[mt][nt][half * 2 + 0] + bb.x,
                                       acc[mt][nt][half * 2 + 1] + bb.y);
                *(float2*)(C + (size_t)r * DIM + c) = o;
            }
        }
    }
}

// ---------------- tf32 flash attention ----------------
// grid (SEQ/128, NB*HEADS); 256 threads = 8 warps; each warp owns 16 q-rows.
// Q fragments live in registers (pre-scaled tf32 from qkv epilogue).
// P moves from S accumulators to PV A-fragments via register shuffles.
__global__ void __launch_bounds__(256) attn_tc()
{
    __shared__ unsigned Ks[64][68];   // 68: (row*68+col)%32 = 4*row+col
    __shared__ unsigned Vs[64][68];

    const int t = threadIdx.x, wid = t >> 5, lane = t & 31;
    const int g = lane >> 2, q4 = lane & 3;
    const int bh = blockIdx.y;
    const int q0 = blockIdx.x * 128 + wid * 16;

    const float* qb = g_q + (size_t)bh * SEQ * DH;
    const float* kb = g_k + (size_t)bh * SEQ * DH;
    const float* vb = g_v + (size_t)bh * SEQ * DH;

    // Q fragments: 8 k-steps over dh, 4 regs each
    unsigned qf[8][4];
    #pragma unroll
    for (int kk = 0; kk < 8; kk++) {
        qf[kk][0] = __float_as_uint(qb[(size_t)(q0 + g) * DH + kk * 8 + q4]);
        qf[kk][1] = __float_as_uint(qb[(size_t)(q0 + g + 8) * DH + kk * 8 + q4]);
        qf[kk][2] = __float_as_uint(qb[(size_t)(q0 + g) * DH + kk * 8 + q4 + 4]);
        qf[kk][3] = __float_as_uint(qb[(size_t)(q0 + g + 8) * DH + kk * 8 + q4 + 4]);
    }

    float o[8][4];
    #pragma unroll
    for (int nt = 0; nt < 8; nt++)
        #pragma unroll
        for (int j = 0; j < 4; j++) o[nt][j] = 0.f;
    float mA = -1e30f, mB = -1e30f, lA = 0.f, lB = 0.f;

    const int lr = t >> 2;        // kv loader: row 0..63
    const int lc = (t & 3) * 4;   // col base; +16*i

    for (int kt = 0; kt < SEQ / 64; kt++) {
        __syncthreads();
        const uint4* kg = (const uint4*)(kb + (size_t)(kt * 64 + lr) * DH + lc);
        const uint4* vg = (const uint4*)(vb + (size_t)(kt * 64 + lr) * DH + lc);
        #pragma unroll
        for (int i = 0; i < 4; i++) *(uint4*)&Ks[lr][lc + 16 * i] = kg[4 * i];
        #pragma unroll
        for (int i = 0; i < 4; i++) *(uint4*)&Vs[lr][lc + 16 * i] = vg[4 * i];
        __syncthreads();

        // S = Q K^T
        float s[8][4];
        #pragma unroll
        for (int nt = 0; nt < 8; nt++)
            #pragma unroll
            for (int j = 0; j < 4; j++) s[nt][j] = 0.f;
        #pragma unroll
        for (int kk = 0; kk < 8; kk++) {
            #pragma unroll
            for (int nt = 0; nt < 8; nt++) {
                unsigned b0 = Ks[nt * 8 + g][kk * 8 + q4];
                unsigned b1 = Ks[nt * 8 + g][kk * 8 + q4 + 4];
                mma8(s[nt], qf[kk], b0, b1);
            }
        }

        // online softmax: thread owns rows g (regs 0,1) and g+8 (regs 2,3)
        float mxA = -1e30f, mxB = -1e30f;
        #pragma unroll
        for (int nt = 0; nt < 8; nt++) {
            mxA = fmaxf(mxA, fmaxf(s[nt][0], s[nt][1]));
            mxB = fmaxf(mxB, fmaxf(s[nt][2], s[nt][3]));
        }
        mxA = fmaxf(mxA, __shfl_xor_sync(0xffffffffu, mxA, 1));
        mxA = fmaxf(mxA, __shfl_xor_sync(0xffffffffu, mxA, 2));
        mxB = fmaxf(mxB, __shfl_xor_sync(0xffffffffu, mxB, 1));
        mxB = fmaxf(mxB, __shfl_xor_sync(0xffffffffu, mxB, 2));
        float mnA = fmaxf(mA, mxA), mnB = fmaxf(mB, mxB);
        float cA = __expf(mA - mnA), cB = __expf(mB - mnB);
        mA = mnA; mB = mnB;
        float sA = 0.f, sB = 0.f;
        #pragma unroll
        for (int nt = 0; nt < 8; nt++) {
            s[nt][0] = __expf(s[nt][0] - mnA); sA += s[nt][0];
            s[nt][1] = __expf(s[nt][1] - mnA); sA += s[nt][1];
            s[nt][2] = __expf(s[nt][2] - mnB); sB += s[nt][2];
            s[nt][3] = __expf(s[nt][3] - mnB); sB += s[nt][3];
        }
        sA += __shfl_xor_sync(0xffffffffu, sA, 1);
        sA += __shfl_xor_sync(0xffffffffu, sA, 2);
        sB += __shfl_xor_sync(0xffffffffu, sB, 1);
        sB += __shfl_xor_sync(0xffffffffu, sB, 2);
        lA = lA * cA + sA;
        lB = lB * cB + sB;
        #pragma unroll
        for (int nt = 0; nt < 8; nt++) {
            o[nt][0] *= cA; o[nt][1] *= cA;
            o[nt][2] *= cB; o[nt][3] *= cB;
        }

        // O += P @ V ; P(C-frag) -> A-frag via shuffles
        #pragma unroll
        for (int kk = 0; kk < 8; kk++) {
            int src0 = (lane & 28) | (q4 >> 1);
            int src1 = src0 + 2;
            float v00 = __shfl_sync(0xffffffffu, s[kk][0], src0);
            float v01 = __shfl_sync(0xffffffffu, s[kk][1], src0);
            float v10 = __shfl_sync(0xffffffffu, s[kk][2], src0);
            float v11 = __shfl_sync(0xffffffffu, s[kk][3], src0);
            float w00 = __shfl_sync(0xffffffffu, s[kk][0], src1);
            float w01 = __shfl_sync(0xffffffffu, s[kk][1], src1);
            float w10 = __shfl_sync(0xffffffffu, s[kk][2], src1);
            float w11 = __shfl_sync(0xffffffffu, s[kk][3], src1);
            bool e = (q4 & 1);
            unsigned af[4];
            af[0] = f2tf(e ? v01 : v00);
            af[1] = f2tf(e ? v11 : v10);
            af[2] = f2tf(e ? w01 : w00);
            af[3] = f2tf(e ? w11 : w10);
            #pragma unroll
            for (int nt = 0; nt < 8; nt++) {
                unsigned b0 = Vs[kk * 8 + q4][nt * 8 + g];
                unsigned b1 = Vs[kk * 8 + q4 + 4][nt * 8 + g];
                mma8(o[nt], af, b0, b1);
            }
        }
    }

    // normalize + write, re-merging heads
    float iA = 1.f / lA, iB = 1.f / lB;
    int b = bh >> 4, h = bh & 15;
    int nA = blockIdx.x * 128 + wid * 16 + g;
    #pragma unroll
    for (int nt = 0; nt < 8; nt++) {
        int dh = nt * 8 + q4 * 2;
        float2 oa = make_float2(o[nt][0] * iA, o[nt][1] * iA);
        float2 ob = make_float2(o[nt][2] * iB, o[nt][3] * iB);
        *(float2*)(g_attn + ((size_t)b * SEQ + nA) * DIM + h * 64 + dh) = oa;
        *(float2*)(g_attn + ((size_t)b * SEQ + nA + 8) * DIM + h * 64 + dh) = ob;
    }
}

// ---------------- launch ----------------
extern "C" void kernel_launch(void* const* d_in, const int* in_sizes, int n_in,
                              void* d_out, int out_size)
{
    const float* x     = (const float*)d_in[0];
    const float* gamma = (const float*)d_in[1];
    const float* beta  = (const float*)d_in[2];
    const float* wq    = (const float*)d_in[3];
    const float* wk    = (const float*)d_in[4];
    const float* wv    = (const float*)d_in[5];
    const float* wo    = (const float*)d_in[6];
    const float* w_out = (const float*)d_in[7];
    const float* b_out = (const float*)d_in[8];
    float* out = (float*)d_out;

    ln_kernel<<<ROWS, 256>>>(x, gamma, beta);
    gemm_wcomb<<<dim3(DIM / BN, DIM / BM), 256>>>(wo, w_out);
    gemm_qkv<<<dim3(DIM / BN, ROWS / BM, 3), 256>>>(wq, wk, wv);
    attn_tc<<<dim3(SEQ / 128, NB * HEADS), 256>>>();
    gemm_out<<<dim3(DIM / BN, ROWS / BM), 256>>>(b_out, out);
}

// round 5
// speedup vs baseline: 3.9140x; 1.1457x over previous
#include <cuda_runtime.h>
#include <cstdint>

#define DIM 1024
#define HEADS 16
#define DH 64
#define SEQ 2048
#define NB 2
#define ROWS (NB * SEQ)        // 4096
#define SCALE 0.125f
#define LNEPS 1e-5f

// ---------------- scratch ----------------
__device__ float g_xn[ROWS * DIM];
__device__ float g_q[ROWS * DIM];      // tf32 bits, pre-scaled; [b*H+h][n][dh]
__device__ float g_k[ROWS * DIM];      // tf32 bits
__device__ float g_v[ROWS * DIM];      // tf32 bits
__device__ float g_attn[ROWS * DIM];   // fp32, heads re-merged [4096,1024]
__device__ float g_wcomb[DIM * DIM];   // wo @ w_out (fp32)

// ---------------- helpers ----------------
__device__ __forceinline__ unsigned f2tf(float x) {
    unsigned u;
    asm("cvt.rna.tf32.f32 %0, %1;" : "=r"(u) : "f"(x));
    return u;
}
__device__ __forceinline__ void mma8(float* c, const unsigned* a, unsigned b0, unsigned b1) {
    asm volatile(
        "mma.sync.aligned.m16n8k8.row.col.f32.tf32.tf32.f32 "
        "{%0,%1,%2,%3}, {%4,%5,%6,%7}, {%8,%9}, {%0,%1,%2,%3};\n"
        : "+f"(c[0]), "+f"(c[1]), "+f"(c[2]), "+f"(c[3])
        : "r"(a[0]), "r"(a[1]), "r"(a[2]), "r"(a[3]), "r"(b0), "r"(b1));
}
__device__ __forceinline__ void cpa16(unsigned dst, const void* src) {
    asm volatile("cp.async.cg.shared.global [%0], [%1], 16;\n" :: "r"(dst), "l"(src));
}

// ---------------- LayerNorm ----------------
__global__ void __launch_bounds__(256) ln_kernel(const float* __restrict__ x,
                                                 const float* __restrict__ gamma,
                                                 const float* __restrict__ beta)
{
    int row = blockIdx.x;
    int t = threadIdx.x;
    const float4* xr = (const float4*)(x + (size_t)row * DIM);
    float4 v = xr[t];
    float s = v.x + v.y + v.z + v.w;
    float ss = v.x * v.x + v.y * v.y + v.z * v.z + v.w * v.w;
    #pragma unroll
    for (int o = 16; o > 0; o >>= 1) {
        s  += __shfl_xor_sync(0xffffffffu, s, o);
        ss += __shfl_xor_sync(0xffffffffu, ss, o);
    }
    __shared__ float sb[8], ssb[8];
    int w = t >> 5, ln = t & 31;
    if (ln == 0) { sb[w] = s; ssb[w] = ss; }
    __syncthreads();
    float tot = 0.f, tot2 = 0.f;
    #pragma unroll
    for (int i = 0; i < 8; i++) { tot += sb[i]; tot2 += ssb[i]; }
    float mu = tot * (1.f / DIM);
    float var = tot2 * (1.f / DIM) - mu * mu;
    float rs = rsqrtf(var + LNEPS);
    float4 g = ((const float4*)gamma)[t];
    float4 bb = ((const float4*)beta)[t];
    float4 o;
    o.x = (v.x - mu) * rs * g.x + bb.x;
    o.y = (v.y - mu) * rs * g.y + bb.y;
    o.z = (v.z - mu) * rs * g.z + bb.z;
    o.w = (v.w - mu) * rs * g.w + bb.w;
    ((float4*)(g_xn + (size_t)row * DIM))[t] = o;
}

// ---------------- tf32 tensor-core GEMM core ----------------
#define BM 128
#define BN 128
#define BK 32
#define APAD 36     // bank = 4*row + col -> frag loads conflict-free
#define BPAD 136    // bank = 8*row + col -> frag loads conflict-free

__device__ __forceinline__ void gemm_tc_core(const float* __restrict__ A,
                                             const float* __restrict__ B,
                                             int K, int N, float acc[2][8][4])
{
    __shared__ unsigned As[BM][APAD];
    __shared__ unsigned Bs[BK][BPAD];
    const int t = threadIdx.x;
    const int wid = t >> 5, lane = t & 31;
    const int g = lane >> 2, q4 = lane & 3;
    const int wm = wid & 3, wn = wid >> 2;
    const int row0 = blockIdx.y * BM, col0 = blockIdx.x * BN;

    const int arow = t >> 3, acol = (t & 7) * 4;
    const int brow = t >> 5, bcol = (t & 31) * 4;

    const float* Ap = A + (size_t)(row0 + arow) * K + acol;
    const float* Bp = B + (size_t)brow * N + col0 + bcol;

    float4 la[4], lb[4];
    #pragma unroll
    for (int i = 0; i < 4; i++) la[i] = *(const float4*)(Ap + (size_t)(32 * i) * K);
    #pragma unroll
    for (int i = 0; i < 4; i++) lb[i] = *(const float4*)(Bp + (size_t)(8 * i) * N);

    for (int k0 = 0; k0 < K; k0 += BK) {
        __syncthreads();
        #pragma unroll
        for (int i = 0; i < 4; i++) {
            uint4 vv;
            vv.x = f2tf(la[i].x); vv.y = f2tf(la[i].y);
            vv.z = f2tf(la[i].z); vv.w = f2tf(la[i].w);
            *(uint4*)&As[arow + 32 * i][acol] = vv;
        }
        #pragma unroll
        for (int i = 0; i < 4; i++) {
            uint4 vv;
            vv.x = f2tf(lb[i].x); vv.y = f2tf(lb[i].y);
            vv.z = f2tf(lb[i].z); vv.w = f2tf(lb[i].w);
            *(uint4*)&Bs[brow + 8 * i][bcol] = vv;
        }
        __syncthreads();
        if (k0 + BK < K) {
            #pragma unroll
            for (int i = 0; i < 4; i++)
                la[i] = *(const float4*)(Ap + k0 + BK + (size_t)(32 * i) * K);
            #pragma unroll
            for (int i = 0; i < 4; i++)
                lb[i] = *(const float4*)(Bp + (size_t)(k0 + BK + 8 * i) * N);
        }
        #pragma unroll
        for (int kk = 0; kk < 4; kk++) {
            unsigned af[2][4];
            #pragma unroll
            for (int mt = 0; mt < 2; mt++) {
                int r = wm * 32 + mt * 16;
                af[mt][0] = As[r + g][kk * 8 + q4];
                af[mt][1] = As[r + g + 8][kk * 8 + q4];
                af[mt][2] = As[r + g][kk * 8 + q4 + 4];
                af[mt][3] = As[r + g + 8][kk * 8 + q4 + 4];
            }
            #pragma unroll
            for (int nt = 0; nt < 8; nt++) {
                int cb = wn * 64 + nt * 8 + g;
                unsigned b0 = Bs[kk * 8 + q4][cb];
                unsigned b1 = Bs[kk * 8 + q4 + 4][cb];
                mma8(acc[0][nt], af[0], b0, b1);
                mma8(acc[1][nt], af[1], b0, b1);
            }
        }
    }
}

// ---------------- QKV projection ----------------
__global__ void __launch_bounds__(256) gemm_qkv(const float* __restrict__ wq,
                                                const float* __restrict__ wk,
                                                const float* __restrict__ wv)
{
    float acc[2][8][4] = {};
    const float* W = (blockIdx.z == 0) ? wq : (blockIdx.z == 1) ? wk : wv;
    gemm_tc_core(g_xn, W, DIM, DIM, acc);
    float* dst = (blockIdx.z == 0) ? g_q : (blockIdx.z == 1) ? g_k : g_v;
    float sc = (blockIdx.z == 0) ? SCALE : 1.f;

    const int t = threadIdx.x, wid = t >> 5, lane = t & 31;
    const int g = lane >> 2, q4 = lane & 3;
    const int wm = wid & 3, wn = wid >> 2;
    #pragma unroll
    for (int mt = 0; mt < 2; mt++) {
        #pragma unroll
        for (int nt = 0; nt < 8; nt++) {
            int cglob = blockIdx.x * BN + wn * 64 + nt * 8 + q4 * 2;
            int h = cglob >> 6, dh = cglob & 63;
            #pragma unroll
            for (int half = 0; half < 2; half++) {
                int m = blockIdx.y * BM + wm * 32 + mt * 16 + g + half * 8;
                int b = m >> 11, n = m & (SEQ - 1);
                float2 o;
                o.x = __uint_as_float(f2tf(acc[mt][nt][half * 2 + 0] * sc));
                o.y = __uint_as_float(f2tf(acc[mt][nt][half * 2 + 1] * sc));
                *(float2*)(dst + ((size_t)(b * HEADS + h) * SEQ + n) * DH + dh) = o;
            }
        }
    }
}

// ---------------- wcomb = wo @ w_out ----------------
__global__ void __launch_bounds__(256) gemm_wcomb(const float* __restrict__ wo,
                                                  const float* __restrict__ wout)
{
    float acc[2][8][4] = {};
    gemm_tc_core(wo, wout, DIM, DIM, acc);
    const int t = threadIdx.x, wid = t >> 5, lane = t & 31;
    const int g = lane >> 2, q4 = lane & 3;
    const int wm = wid & 3, wn = wid >> 2;
    #pragma unroll
    for (int mt = 0; mt < 2; mt++) {
        #pragma unroll
        for (int nt = 0; nt < 8; nt++) {
            int c = blockIdx.x * BN + wn * 64 + nt * 8 + q4 * 2;
            #pragma unroll
            for (int half = 0; half < 2; half++) {
                int r = blockIdx.y * BM + wm * 32 + mt * 16 + g + half * 8;
                float2 o = make_float2(acc[mt][nt][half * 2 + 0], acc[mt][nt][half * 2 + 1]);
                *(float2*)(g_wcomb + (size_t)r * DIM + c) = o;
            }
        }
    }
}

// ---------------- final projection ----------------
__global__ void __launch_bounds__(256) gemm_out(const float* __restrict__ bias,
                                                float* __restrict__ C)
{
    float acc[2][8][4] = {};
    gemm_tc_core(g_attn, g_wcomb, DIM, DIM, acc);
    const int t = threadIdx.x, wid = t >> 5, lane = t & 31;
    const int g = lane >> 2, q4 = lane & 3;
    const int wm = wid & 3, wn = wid >> 2;
    #pragma unroll
    for (int mt = 0; mt < 2; mt++) {
        #pragma unroll
        for (int nt = 0; nt < 8; nt++) {
            int c = blockIdx.x * BN + wn * 64 + nt * 8 + q4 * 2;
            float2 bb = *(const float2*)(bias + c);
            #pragma unroll
            for (int half = 0; half < 2; half++) {
                int r = blockIdx.y * BM + wm * 32 + mt * 16 + g + half * 8;
                float2 o = make_float2(acc[mt][nt][half * 2 + 0] + bb.x,
                                       acc[mt][nt][half * 2 + 1] + bb.y);
                *(float2*)(C + (size_t)r * DIM + c) = o;
            }
        }
    }
}

// ---------------- tf32 flash attention, cp.async double-buffered ----------------
// grid (SEQ/128, NB*HEADS); 256 threads = 8 warps; warp owns 16 q-rows.
// K pad 68 -> frag bank = 4g+q4 (all distinct). V pad 72 -> frag bank = 8q4+g (all distinct).
#define KPAD 68
#define VPAD 72
#define KW (64 * KPAD)              // words per K buffer
#define VW (64 * VPAD)              // words per V buffer
#define ATTN_SMEM ((2 * KW + 2 * VW) * 4)   // 71680 bytes

__global__ void __launch_bounds__(256) attn_tc()
{
    extern __shared__ unsigned dsm[];

    const int t = threadIdx.x, wid = t >> 5, lane = t & 31;
    const int g = lane >> 2, q4 = lane & 3;
    const int bh = blockIdx.y;
    const int q0 = blockIdx.x * 128 + wid * 16;

    const float* qb = g_q + (size_t)bh * SEQ * DH;
    const float* kb = g_k + (size_t)bh * SEQ * DH;
    const float* vb = g_v + (size_t)bh * SEQ * DH;

    // loader: thread -> row lr (0..63), col chunk base lc (+16*i)
    const int lr = t >> 2, lc = (t & 3) * 4;
    unsigned kst[2], vst[2];
    kst[0] = (unsigned)__cvta_generic_to_shared(dsm + lr * KPAD + lc);
    kst[1] = kst[0] + KW * 4;
    vst[0] = (unsigned)__cvta_generic_to_shared(dsm + 2 * KW + lr * VPAD + lc);
    vst[1] = vst[0] + VW * 4;
    const float* kgp = kb + (size_t)lr * DH + lc;
    const float* vgp = vb + (size_t)lr * DH + lc;

    // Q fragments in registers (pre-scaled tf32 from qkv epilogue)
    unsigned qf[8][4];
    #pragma unroll
    for (int kk = 0; kk < 8; kk++) {
        qf[kk][0] = __float_as_uint(qb[(size_t)(q0 + g) * DH + kk * 8 + q4]);
        qf[kk][1] = __float_as_uint(qb[(size_t)(q0 + g + 8) * DH + kk * 8 + q4]);
        qf[kk][2] = __float_as_uint(qb[(size_t)(q0 + g) * DH + kk * 8 + q4 + 4]);
        qf[kk][3] = __float_as_uint(qb[(size_t)(q0 + g + 8) * DH + kk * 8 + q4 + 4]);
    }

    float o[8][4];
    #pragma unroll
    for (int nt = 0; nt < 8; nt++)
        #pragma unroll
        for (int j = 0; j < 4; j++) o[nt][j] = 0.f;
    float mA = -1e30f, mB = -1e30f, lA = 0.f, lB = 0.f;

    // prologue: tile 0 -> buffer 0
    #pragma unroll
    for (int i = 0; i < 4; i++) cpa16(kst[0] + i * 64, kgp + 16 * i);
    #pragma unroll
    for (int i = 0; i < 4; i++) cpa16(vst[0] + i * 64, vgp + 16 * i);
    asm volatile("cp.async.commit_group;\n");

    for (int kt = 0; kt < SEQ / 64; kt++) {
        const int cur = kt & 1;
        if (kt + 1 < SEQ / 64) {
            const float* kn = kgp + (size_t)(kt + 1) * 64 * DH;
            const float* vn = vgp + (size_t)(kt + 1) * 64 * DH;
            #pragma unroll
            for (int i = 0; i < 4; i++) cpa16(kst[cur ^ 1] + i * 64, kn + 16 * i);
            #pragma unroll
            for (int i = 0; i < 4; i++) cpa16(vst[cur ^ 1] + i * 64, vn + 16 * i);
            asm volatile("cp.async.commit_group;\n");
            asm volatile("cp.async.wait_group 1;\n");
        } else {
            asm volatile("cp.async.wait_group 0;\n");
        }
        __syncthreads();

        const unsigned* Ks = dsm + (size_t)cur * KW;
        const unsigned* Vs = dsm + 2 * KW + (size_t)cur * VW;

        // S = Q K^T
        float s[8][4];
        #pragma unroll
        for (int nt = 0; nt < 8; nt++)
            #pragma unroll
            for (int j = 0; j < 4; j++) s[nt][j] = 0.f;
        #pragma unroll
        for (int kk = 0; kk < 8; kk++) {
            #pragma unroll
            for (int nt = 0; nt < 8; nt++) {
                unsigned b0 = Ks[(nt * 8 + g) * KPAD + kk * 8 + q4];
                unsigned b1 = Ks[(nt * 8 + g) * KPAD + kk * 8 + q4 + 4];
                mma8(s[nt], qf[kk], b0, b1);
            }
        }

        // online softmax: thread owns rows g (regs 0,1) and g+8 (regs 2,3)
        float mxA = -1e30f, mxB = -1e30f;
        #pragma unroll
        for (int nt = 0; nt < 8; nt++) {
            mxA = fmaxf(mxA, fmaxf(s[nt][0], s[nt][1]));
            mxB = fmaxf(mxB, fmaxf(s[nt][2], s[nt][3]));
        }
        mxA = fmaxf(mxA, __shfl_xor_sync(0xffffffffu, mxA, 1));
        mxA = fmaxf(mxA, __shfl_xor_sync(0xffffffffu, mxA, 2));
        mxB = fmaxf(mxB, __shfl_xor_sync(0xffffffffu, mxB, 1));
        mxB = fmaxf(mxB, __shfl_xor_sync(0xffffffffu, mxB, 2));
        float mnA = fmaxf(mA, mxA), mnB = fmaxf(mB, mxB);
        float cA = __expf(mA - mnA), cB = __expf(mB - mnB);
        mA = mnA; mB = mnB;
        float sA = 0.f, sB = 0.f;
        #pragma unroll
        for (int nt = 0; nt < 8; nt++) {
            s[nt][0] = __expf(s[nt][0] - mnA); sA += s[nt][0];
            s[nt][1] = __expf(s[nt][1] - mnA); sA += s[nt][1];
            s[nt][2] = __expf(s[nt][2] - mnB); sB += s[nt][2];
            s[nt][3] = __expf(s[nt][3] - mnB); sB += s[nt][3];
        }
        sA += __shfl_xor_sync(0xffffffffu, sA, 1);
        sA += __shfl_xor_sync(0xffffffffu, sA, 2);
        sB += __shfl_xor_sync(0xffffffffu, sB, 1);
        sB += __shfl_xor_sync(0xffffffffu, sB, 2);
        lA = lA * cA + sA;
        lB = lB * cB + sB;
        #pragma unroll
        for (int nt = 0; nt < 8; nt++) {
            o[nt][0] *= cA; o[nt][1] *= cA;
            o[nt][2] *= cB; o[nt][3] *= cB;
        }

        // O += P @ V ; P(C-frag) -> A-frag via shuffles
        #pragma unroll
        for (int kk = 0; kk < 8; kk++) {
            int src0 = (lane & 28) | (q4 >> 1);
            int src1 = src0 + 2;
            float v00 = __shfl_sync(0xffffffffu, s[kk][0], src0);
            float v01 = __shfl_sync(0xffffffffu, s[kk][1], src0);
            float v10 = __shfl_sync(0xffffffffu, s[kk][2], src0);
            float v11 = __shfl_sync(0xffffffffu, s[kk][3], src0);
            float w00 = __shfl_sync(0xffffffffu, s[kk][0], src1);
            float w01 = __shfl_sync(0xffffffffu, s[kk][1], src1);
            float w10 = __shfl_sync(0xffffffffu, s[kk][2], src1);
            float w11 = __shfl_sync(0xffffffffu, s[kk][3], src1);
            bool e = (q4 & 1);
            unsigned af[4];
            af[0] = f2tf(e ? v01 : v00);
            af[1] = f2tf(e ? v11 : v10);
            af[2] = f2tf(e ? w01 : w00);
            af[3] = f2tf(e ? w11 : w10);
            #pragma unroll
            for (int nt = 0; nt < 8; nt++) {
                unsigned b0 = Vs[(kk * 8 + q4) * VPAD + nt * 8 + g];
                unsigned b1 = Vs[(kk * 8 + q4 + 4) * VPAD + nt * 8 + g];
                mma8(o[nt], af, b0, b1);
            }
        }
        __syncthreads();
    }

    // normalize + write, re-merging heads
    float iA = 1.f / lA, iB = 1.f / lB;
    int b = bh >> 4, h = bh & 15;
    int nA = blockIdx.x * 128 + wid * 16 + g;
    #pragma unroll
    for (int nt = 0; nt < 8; nt++) {
        int dh = nt * 8 + q4 * 2;
        float2 oa = make_float2(o[nt][0] * iA, o[nt][1] * iA);
        float2 ob = make_float2(o[nt][2] * iB, o[nt][3] * iB);
        *(float2*)(g_attn + ((size_t)b * SEQ + nA) * DIM + h * 64 + dh) = oa;
        *(float2*)(g_attn + ((size_t)b * SEQ + nA + 8) * DIM + h * 64 + dh) = ob;
    }
}

// ---------------- launch ----------------
extern "C" void kernel_launch(void* const* d_in, const int* in_sizes, int n_in,
                              void* d_out, int out_size)
{
    const float* x     = (const float*)d_in[0];
    const float* gamma = (const float*)d_in[1];
    const float* beta  = (const float*)d_in[2];
    const float* wq    = (const float*)d_in[3];
    const float* wk    = (const float*)d_in[4];
    const float* wv    = (const float*)d_in[5];
    const float* wo    = (const float*)d_in[6];
    const float* w_out = (const float*)d_in[7];
    const float* b_out = (const float*)d_in[8];
    float* out = (float*)d_out;

    cudaFuncSetAttribute(attn_tc, cudaFuncAttributeMaxDynamicSharedMemorySize, ATTN_SMEM);

    ln_kernel<<<ROWS, 256>>>(x, gamma, beta);
    gemm_wcomb<<<dim3(DIM / BN, DIM / BM), 256>>>(wo, w_out);
    gemm_qkv<<<dim3(DIM / BN, ROWS / BM, 3), 256>>>(wq, wk, wv);
    attn_tc<<<dim3(SEQ / 128, NB * HEADS), 256, ATTN_SMEM>>>();
    gemm_out<<<dim3(DIM / BN, ROWS / BM), 256>>>(b_out, out);
}